// round 9
// baseline (speedup 1.0000x reference)
#include <cuda_runtime.h>
#include <cuda_bf16.h>
#include <cuda_fp16.h>
#include <cstdint>

#define NB 64
#define NT 512
#define NI 128
#define NH 256
#define NR 20
#define NDA 50
#define NC 10
#define G4 1024

// ----------------------------- device scratch ------------------------------
__device__ float  g_S   [NB * NR * NT];             // [b][r][t]
__device__ float  g_E   [NB * NT * NR];             // [b][t][r]
__device__ float  g_Dinv[NB * NT * NR];             // [b][t][r]
__device__ float  g_MT  [(size_t)NT * NI * NB];     // [t][i][b]
__device__ __half g_hh  [2][NH * 64];               // [buf][hd*64 + b]
__device__ unsigned g_flags[128 * 8];               // padded: flag for block bk at [bk*8]

__device__ __forceinline__ void ffma2(unsigned long long& acc,
                                      unsigned long long a,
                                      unsigned long long b) {
    asm("fma.rn.f32x2 %0, %1, %2, %0;" : "+l"(acc) : "l"(a), "l"(b));
}
__device__ __forceinline__ float sigf(float v) {
    return __fdividef(1.0f, 1.0f + __expf(-v));
}
__device__ __forceinline__ float tanhfast(float v) {
    float ax = fabsf(v);
    float e = __expf(-2.0f * ax);
    float t = __fdividef(1.0f - e, 1.0f + e);
    return copysignf(t, v);
}

// ------------------------------ K1: scores (+init) --------------------------
__global__ void k_scores(const float* __restrict__ x,
                         const float* __restrict__ W1, const float* __restrict__ b1,
                         const float* __restrict__ W2, const float* __restrict__ b2) {
    __shared__ float W1s[NDA][NI + 1];
    __shared__ float W2s[NR][NDA + 1];
    __shared__ float b1s[NDA];
    __shared__ float b2s[NR];
    __shared__ float xr[8][NI];
    __shared__ float ssm[8][NDA + 1];
    int tid = threadIdx.x;

    if (blockIdx.x == 0) {
        for (int j = tid; j < NH * 64; j += 256) g_hh[0][j] = __float2half(1.0f);
        for (int j = tid; j < 128 * 8; j += 256) g_flags[j] = 0u;
    }

    for (int idx = tid; idx < NDA * NI; idx += 256) W1s[idx / NI][idx % NI] = W1[idx];
    for (int idx = tid; idx < NR * NDA; idx += 256) W2s[idx / NDA][idx % NDA] = W2[idx];
    if (tid < NDA) b1s[tid] = b1[tid];
    if (tid < NR)  b2s[tid] = b2[tid];
    __syncthreads();

    int w = tid >> 5, lane = tid & 31;
    int bt = blockIdx.x * 8 + w;
    const float* xp = x + (size_t)bt * NI;
    for (int i = lane; i < NI; i += 32) xr[w][i] = xp[i];
    __syncwarp();
    for (int d = lane; d < NDA; d += 32) {
        float acc = b1s[d];
        #pragma unroll 16
        for (int i = 0; i < NI; i++) acc = fmaf(xr[w][i], W1s[d][i], acc);
        ssm[w][d] = tanhf(acc);
    }
    __syncwarp();
    if (lane < NR) {
        float acc = b2s[lane];
        #pragma unroll
        for (int d = 0; d < NDA; d++) acc = fmaf(ssm[w][d], W2s[lane][d], acc);
        int b = bt >> 9, t = bt & 511;
        g_S[((size_t)b * NR + lane) * NT + t] = acc;
    }
}

// --------------- K2: max over t, exp, prefix-sum denominators ---------------
__global__ void k_maxexpdinv() {
    int br = blockIdx.x;
    int b = br / NR, r = br % NR;
    int tid = threadIdx.x;
    int w = tid >> 5, lane = tid & 31;
    const float* Sp = g_S + (size_t)br * NT;
    float4 v = *(const float4*)(Sp + 4 * tid);

    __shared__ float red[4];
    __shared__ float wsum[4];
    float m = fmaxf(fmaxf(v.x, v.y), fmaxf(v.z, v.w));
    for (int o = 16; o; o >>= 1) m = fmaxf(m, __shfl_xor_sync(~0u, m, o));
    if (lane == 0) red[w] = m;
    __syncthreads();
    m = fmaxf(fmaxf(red[0], red[1]), fmaxf(red[2], red[3]));

    float e0 = __expf(v.x - m), e1 = __expf(v.y - m);
    float e2 = __expf(v.z - m), e3 = __expf(v.w - m);
    float ls = e0 + e1 + e2 + e3;

    float s = ls;
    for (int o = 1; o < 32; o <<= 1) {
        float n = __shfl_up_sync(~0u, s, o);
        if (lane >= o) s += n;
    }
    if (lane == 31) wsum[w] = s;
    __syncthreads();
    float base = 0.0f;
    #pragma unroll
    for (int ww = 0; ww < 4; ww++) if (ww < w) base += wsum[ww];

    float excl = base + s - ls;
    float d0 = excl + e0;
    float d1 = d0 + e1;
    float d2 = d1 + e2;
    float d3 = d2 + e3;

    int t0 = 4 * tid;
    size_t a0 = ((size_t)b * NT + t0) * NR + r;
    g_E[a0]            = e0;
    g_E[a0 + NR]       = e1;
    g_E[a0 + 2 * NR]   = e2;
    g_E[a0 + 3 * NR]   = e3;
    g_Dinv[a0]          = __fdividef(1.0f, d0);
    g_Dinv[a0 + NR]     = __fdividef(1.0f, d1);
    g_Dinv[a0 + 2 * NR] = __fdividef(1.0f, d2);
    g_Dinv[a0 + 3 * NR] = __fdividef(1.0f, d3);
}

// ------- K3: M via per-chunk recompute; writes MT[t][i][b] directly ---------
__global__ void k_attnM(const float* __restrict__ x) {
    int bc = blockIdx.x;
    int b = bc >> 3, c = bc & 7;
    int i = threadIdx.x;
    float N[NR];
    #pragma unroll
    for (int r = 0; r < NR; r++) N[r] = 0.0f;

    const float* xb = x + ((size_t)b * NT) * NI + i;
    const float* Eb = g_E + ((size_t)b * NT) * NR;
    const float* Db = g_Dinv + ((size_t)b * NT) * NR;

    int tstart = c * 64;
    for (int t = 0; t < tstart; t++) {
        float xv = xb[(size_t)t * NI];
        #pragma unroll
        for (int r = 0; r < NR; r++)
            N[r] = fmaf(Eb[(size_t)t * NR + r], xv, N[r]);
    }
    for (int tl = 0; tl < 64; tl++) {
        int t = tstart + tl;
        float xv = xb[(size_t)t * NI];
        float acc = 0.0f;
        #pragma unroll
        for (int r = 0; r < NR; r++) {
            N[r] = fmaf(Eb[(size_t)t * NR + r], xv, N[r]);
            acc = fmaf(N[r], Db[(size_t)t * NR + r], acc);
        }
        g_MT[((size_t)t * NI + i) * 64 + b] = acc * 0.05f;
    }
}

// ---------------- K4: fused LSTM, producer-flag overlapped h exchange -------
// 128 persistent blocks x 256 threads. Block bk owns h-dims {2bk,2bk+1} -> 8 cols.
// Compute decomposition: p=tid&15 (4 batches), qh=(tid>>4)&1 (4 cols), wid=tid>>5
// (k-octant of 32). Thread = 4 cols x 4 b = 8 f32x2 accumulators.
// smem floats: hs 256*68 | Ws2 4096 | Wis2 2048 | Ms 8192 | gred 4096 | csm 128 | bs 8
#define HS_STRIDE 68
#define LSTM_SMEM ((256 * HS_STRIDE + 4096 + 2048 + 8192 + 4096 + 128 + 8) * 4)

__global__ void __launch_bounds__(256, 1) k_lstm(const float* __restrict__ Whh,
                                                 const float* __restrict__ Wih,
                                                 const float* __restrict__ bias) {
    extern __shared__ float sm[];
    float* hs   = sm;                        // [k=256][HS_STRIDE]
    float* Ws2  = hs + 256 * HS_STRIDE;      // Whh slice pair-dup [k=256][16]
    float* Wis2 = Ws2 + 4096;                // Wih slice pair-dup [i=128][16]
    float* Ms   = Wis2 + 2048;               // parked M_{t+1} [i=128][b=64]
    float* gred = Ms + 8192;                 // [oct=8][c=8][b=64]
    float* csm  = gred + 4096;               // c state (128)
    float* bs   = csm + 128;                 // bias slice (8)

    int bk = blockIdx.x;
    int tid = threadIdx.x;
    int p = tid & 15, qh = (tid >> 4) & 1, wid = tid >> 5;

    for (int idx = tid; idx < NH * 8; idx += 256) {
        int k = idx >> 3, c = idx & 7;
        float w = Whh[(size_t)k * G4 + (c & 3) * NH + 2 * bk + (c >> 2)];
        Ws2[idx * 2] = w;
        Ws2[idx * 2 + 1] = w;
    }
    for (int idx = tid; idx < NI * 8; idx += 256) {
        int k = idx >> 3, c = idx & 7;
        float w = Wih[(size_t)k * G4 + (c & 3) * NH + 2 * bk + (c >> 2)];
        Wis2[idx * 2] = w;
        Wis2[idx * 2 + 1] = w;
    }
    if (tid < 8) bs[tid] = bias[(tid & 3) * NH + 2 * bk + (tid >> 2)];
    if (tid < 128) csm[tid] = 1.0f;

    // ---- prologue: stage M_0, compute gx partials for t=0 ----
    {
        float4 rm0[8];
        #pragma unroll
        for (int j = 0; j < 8; j++)
            rm0[j] = __ldcg((const float4*)g_MT + tid + j * 256);
        #pragma unroll
        for (int j = 0; j < 8; j++)
            *((float4*)Ms + tid + j * 256) = rm0[j];
    }
    __syncthreads();
    unsigned long long gx[8];
    #pragma unroll
    for (int j = 0; j < 8; j++) gx[j] = 0ull;
    {
        const float* mp = Ms + (wid * 16) * 64 + 4 * p;
        const float* wp = Wis2 + (wid * 16) * 16 + 8 * qh;
        #pragma unroll
        for (int k = 0; k < 16; k++) {
            ulonglong2 mv = *(const ulonglong2*)mp;
            ulonglong2 w0 = *(const ulonglong2*)wp;
            ulonglong2 w1 = *(const ulonglong2*)(wp + 4);
            ffma2(gx[0], mv.x, w0.x); ffma2(gx[1], mv.y, w0.x);
            ffma2(gx[2], mv.x, w0.y); ffma2(gx[3], mv.y, w0.y);
            ffma2(gx[4], mv.x, w1.x); ffma2(gx[5], mv.y, w1.x);
            ffma2(gx[6], mv.x, w1.y); ffma2(gx[7], mv.y, w1.y);
            mp += 64; wp += 16;
        }
    }

    int bbg = tid & 63, hig = (tid >> 6) & 1;   // gate-phase mapping (tid<128)
    const unsigned* myflag = &g_flags[(tid >> 1) * 8];

    for (int t = 0; t < NT; t++) {
        const __half* hin = g_hh[t & 1];
        __half* hout = g_hh[(t + 1) & 1];
        const float* mnext = g_MT + (size_t)((t + 1) & (NT - 1)) * (NI * 64);

        // early-issue M_{t+1}
        float4 rm[8];
        #pragma unroll
        for (int j = 0; j < 8; j++)
            rm[j] = __ldcg((const float4*)mnext + tid + j * 256);

        // poll ONLY my producer's flag, then fetch my h row (overlaps straggle)
        {
            unsigned v;
            do {
                asm volatile("ld.acquire.gpu.global.u32 %0, [%1];"
                             : "=r"(v) : "l"(myflag));
            } while (v < (unsigned)t);
        }
        uint4 rh[8];
        #pragma unroll
        for (int j = 0; j < 8; j++)
            rh[j] = __ldcg((const uint4*)(hin + (size_t)tid * 64) + j);
        {
            float* hrow = hs + tid * HS_STRIDE;
            #pragma unroll
            for (int j = 0; j < 8; j++) {
                __half2* hx = (__half2*)&rh[j];
                float2 f0 = __half22float2(hx[0]);
                float2 f1 = __half22float2(hx[1]);
                float2 f2 = __half22float2(hx[2]);
                float2 f3 = __half22float2(hx[3]);
                *(float4*)(hrow + j * 8)     = make_float4(f0.x, f0.y, f1.x, f1.y);
                *(float4*)(hrow + j * 8 + 4) = make_float4(f2.x, f2.y, f3.x, f3.y);
            }
        }
        __syncthreads();                               // (1) hs ready

        unsigned long long a[8];
        #pragma unroll
        for (int j = 0; j < 8; j++) a[j] = gx[j];
        {   // recurrent dot: this warp's unique k-octant (32 k)
            const float* hp = hs + (wid * 32) * HS_STRIDE + 4 * p;
            const float* wp = Ws2 + (wid * 32) * 16 + 8 * qh;
            #pragma unroll
            for (int k = 0; k < 32; k++) {
                ulonglong2 hv = *(const ulonglong2*)hp;
                ulonglong2 w0 = *(const ulonglong2*)wp;
                ulonglong2 w1 = *(const ulonglong2*)(wp + 4);
                ffma2(a[0], hv.x, w0.x); ffma2(a[1], hv.y, w0.x);
                ffma2(a[2], hv.x, w0.y); ffma2(a[3], hv.y, w0.y);
                ffma2(a[4], hv.x, w1.x); ffma2(a[5], hv.y, w1.x);
                ffma2(a[6], hv.x, w1.y); ffma2(a[7], hv.y, w1.y);
                hp += HS_STRIDE; wp += 16;
            }
        }
        {
            float* gr = gred + (wid * 8 + 4 * qh) * 64 + 4 * p;
            ulonglong2 v;
            v.x = a[0]; v.y = a[1]; *(ulonglong2*)gr         = v;
            v.x = a[2]; v.y = a[3]; *(ulonglong2*)(gr + 64)  = v;
            v.x = a[4]; v.y = a[5]; *(ulonglong2*)(gr + 128) = v;
            v.x = a[6]; v.y = a[7]; *(ulonglong2*)(gr + 192) = v;
        }
        // park M_{t+1} (read by gx after sync(3) -> ordered)
        #pragma unroll
        for (int j = 0; j < 8; j++)
            *((float4*)Ms + tid + j * 256) = rm[j];
        __syncthreads();                               // (2) gred + Ms ready

        if (tid < 128) {
            float gv[4];
            #pragma unroll
            for (int g = 0; g < 4; g++) {
                int c = hig * 4 + g;
                float s = 0.0f;
                #pragma unroll
                for (int o = 0; o < 8; o++) s += gred[(o * 8 + c) * 64 + bbg];
                gv[g] = s + bs[c];
            }
            float i_t = sigf(gv[0]);
            float f_t = sigf(gv[1]);
            float g_t = tanhfast(gv[2]);
            float o_t = sigf(gv[3]);
            float cc = f_t * csm[tid] + i_t * g_t;
            csm[tid] = cc;
            unsigned short h16 = __half_as_ushort(__float2half_rn(o_t * tanhfast(cc)));
            const __half* hp = hout + (2 * bk + hig) * 64 + bbg;
            asm volatile("st.global.cg.b16 [%0], %1;" :: "l"(hp), "h"(h16) : "memory");
        }
        __syncthreads();                               // (3) all h stores done

        if (tid == 0)
            asm volatile("st.release.gpu.global.u32 [%0], %1;"
                         :: "l"(&g_flags[bk * 8]), "r"((unsigned)(t + 1)) : "memory");

        // gx for t+1 (runs in the straggle window, after our release)
        #pragma unroll
        for (int j = 0; j < 8; j++) gx[j] = 0ull;
        {
            const float* mp = Ms + (wid * 16) * 64 + 4 * p;
            const float* wp = Wis2 + (wid * 16) * 16 + 8 * qh;
            #pragma unroll
            for (int k = 0; k < 16; k++) {
                ulonglong2 mv = *(const ulonglong2*)mp;
                ulonglong2 w0 = *(const ulonglong2*)wp;
                ulonglong2 w1 = *(const ulonglong2*)(wp + 4);
                ffma2(gx[0], mv.x, w0.x); ffma2(gx[1], mv.y, w0.x);
                ffma2(gx[2], mv.x, w0.y); ffma2(gx[3], mv.y, w0.y);
                ffma2(gx[4], mv.x, w1.x); ffma2(gx[5], mv.y, w1.x);
                ffma2(gx[6], mv.x, w1.y); ffma2(gx[7], mv.y, w1.y);
                mp += 64; wp += 16;
            }
        }
    }
}

// ------------------------------ K5: head + softmax --------------------------
__global__ void k_head(const float* __restrict__ Wfc, const float* __restrict__ bfc,
                       float* __restrict__ out) {
    int b = blockIdx.x;
    int lane = threadIdx.x;
    __shared__ float hsm[NH];
    for (int k = lane; k < NH; k += 32) hsm[k] = __half2float(g_hh[0][k * 64 + b]);
    __syncwarp();
    float l = -1e30f;
    if (lane < NC) {
        float acc = bfc[lane];
        #pragma unroll 8
        for (int k = 0; k < NH; k++) acc = fmaf(hsm[k], Wfc[lane * NH + k], acc);
        l = acc;
    }
    float m = l;
    for (int o = 16; o; o >>= 1) m = fmaxf(m, __shfl_xor_sync(~0u, m, o));
    float e = (lane < NC) ? __expf(l - m) : 0.0f;
    float s = e;
    for (int o = 16; o; o >>= 1) s += __shfl_xor_sync(~0u, s, o);
    if (lane < NC) out[b * NC + lane] = e / s;
}

// ------------------------------ launch --------------------------------------
extern "C" void kernel_launch(void* const* d_in, const int* in_sizes, int n_in,
                              void* d_out, int out_size) {
    const float* x    = (const float*)d_in[0];
    const float* W_ih = (const float*)d_in[1];
    const float* W_hh = (const float*)d_in[2];
    const float* b    = (const float*)d_in[3];
    const float* W1   = (const float*)d_in[4];
    const float* b1   = (const float*)d_in[5];
    const float* W2   = (const float*)d_in[6];
    const float* b2   = (const float*)d_in[7];
    const float* Wfc  = (const float*)d_in[8];
    const float* bfc  = (const float*)d_in[9];
    float* out = (float*)d_out;

    cudaFuncSetAttribute(k_lstm, cudaFuncAttributeMaxDynamicSharedMemorySize, LSTM_SMEM);

    k_scores<<<4096, 256>>>(x, W1, b1, W2, b2);            // idx 0
    k_maxexpdinv<<<NB * NR, 128>>>();                      // idx 1
    k_attnM<<<NB * 8, 128>>>(x);                           // idx 2
    k_lstm<<<128, 256, LSTM_SMEM>>>(W_hh, W_ih, b);        // idx 3 (ncu slot)
    k_head<<<NB, 32>>>(Wfc, bfc, out);                     // idx 4
}

// round 10
// speedup vs baseline: 1.0201x; 1.0201x over previous
#include <cuda_runtime.h>
#include <cuda_bf16.h>
#include <cstdint>

#define NB 64
#define NT 512
#define NI 128
#define NH 256
#define NR 20
#define NDA 50
#define NC 10
#define G4 1024
#define CLS 8

// ----------------------------- device scratch ------------------------------
__device__ float g_S   [NB * NR * NT];              // [b][r][t]
__device__ float g_E   [NB * NT * NR];              // [b][t][r]
__device__ float g_Dinv[NB * NT * NR];              // [b][t][r]
__device__ float g_MT  [(size_t)NT * NI * NB];      // [t][i][b]
__device__ float g_hT  [NH * 64];                   // final h: [hd][b]

__device__ __forceinline__ void ffma2(unsigned long long& acc,
                                      unsigned long long a,
                                      unsigned long long b) {
    asm("fma.rn.f32x2 %0, %1, %2, %0;" : "+l"(acc) : "l"(a), "l"(b));
}
__device__ __forceinline__ unsigned long long dup2(float w) {
    unsigned long long r;
    asm("mov.b64 %0, {%1, %1};" : "=l"(r) : "f"(w));
    return r;
}
__device__ __forceinline__ float sigf(float v) {
    return __fdividef(1.0f, 1.0f + __expf(-v));
}
__device__ __forceinline__ float tanhfast(float v) {
    float ax = fabsf(v);
    float e = __expf(-2.0f * ax);
    float t = __fdividef(1.0f - e, 1.0f + e);
    return copysignf(t, v);
}
__device__ __forceinline__ uint32_t smem_u32(const void* p) {
    uint32_t a;
    asm("{ .reg .u64 t; cvta.to.shared.u64 t, %1; cvt.u32.u64 %0, t; }"
        : "=r"(a) : "l"(p));
    return a;
}
__device__ __forceinline__ void st_cluster_f32(uint32_t addr, int rank, float v) {
    uint32_t r;
    asm volatile("mapa.shared::cluster.u32 %0, %1, %2;" : "=r"(r) : "r"(addr), "r"(rank));
    asm volatile("st.shared::cluster.f32 [%0], %1;" :: "r"(r), "f"(v) : "memory");
}

// ------------------------------ K1: scores ----------------------------------
__global__ void k_scores(const float* __restrict__ x,
                         const float* __restrict__ W1, const float* __restrict__ b1,
                         const float* __restrict__ W2, const float* __restrict__ b2) {
    __shared__ float W1s[NDA][NI + 1];
    __shared__ float W2s[NR][NDA + 1];
    __shared__ float b1s[NDA];
    __shared__ float b2s[NR];
    __shared__ float xr[8][NI];
    __shared__ float ssm[8][NDA + 1];
    int tid = threadIdx.x;

    for (int idx = tid; idx < NDA * NI; idx += 256) W1s[idx / NI][idx % NI] = W1[idx];
    for (int idx = tid; idx < NR * NDA; idx += 256) W2s[idx / NDA][idx % NDA] = W2[idx];
    if (tid < NDA) b1s[tid] = b1[tid];
    if (tid < NR)  b2s[tid] = b2[tid];
    __syncthreads();

    int w = tid >> 5, lane = tid & 31;
    int bt = blockIdx.x * 8 + w;
    const float* xp = x + (size_t)bt * NI;
    for (int i = lane; i < NI; i += 32) xr[w][i] = xp[i];
    __syncwarp();
    for (int d = lane; d < NDA; d += 32) {
        float acc = b1s[d];
        #pragma unroll 16
        for (int i = 0; i < NI; i++) acc = fmaf(xr[w][i], W1s[d][i], acc);
        ssm[w][d] = tanhf(acc);
    }
    __syncwarp();
    if (lane < NR) {
        float acc = b2s[lane];
        #pragma unroll
        for (int d = 0; d < NDA; d++) acc = fmaf(ssm[w][d], W2s[lane][d], acc);
        int b = bt >> 9, t = bt & 511;
        g_S[((size_t)b * NR + lane) * NT + t] = acc;
    }
}

// --------------- K2: max over t, exp, prefix-sum denominators ---------------
__global__ void k_maxexpdinv() {
    int br = blockIdx.x;
    int b = br / NR, r = br % NR;
    int tid = threadIdx.x;
    int w = tid >> 5, lane = tid & 31;
    const float* Sp = g_S + (size_t)br * NT;
    float4 v = *(const float4*)(Sp + 4 * tid);

    __shared__ float red[4];
    __shared__ float wsum[4];
    float m = fmaxf(fmaxf(v.x, v.y), fmaxf(v.z, v.w));
    for (int o = 16; o; o >>= 1) m = fmaxf(m, __shfl_xor_sync(~0u, m, o));
    if (lane == 0) red[w] = m;
    __syncthreads();
    m = fmaxf(fmaxf(red[0], red[1]), fmaxf(red[2], red[3]));

    float e0 = __expf(v.x - m), e1 = __expf(v.y - m);
    float e2 = __expf(v.z - m), e3 = __expf(v.w - m);
    float ls = e0 + e1 + e2 + e3;

    float s = ls;
    for (int o = 1; o < 32; o <<= 1) {
        float n = __shfl_up_sync(~0u, s, o);
        if (lane >= o) s += n;
    }
    if (lane == 31) wsum[w] = s;
    __syncthreads();
    float base = 0.0f;
    #pragma unroll
    for (int ww = 0; ww < 4; ww++) if (ww < w) base += wsum[ww];

    float excl = base + s - ls;
    float d0 = excl + e0;
    float d1 = d0 + e1;
    float d2 = d1 + e2;
    float d3 = d2 + e3;

    int t0 = 4 * tid;
    size_t a0 = ((size_t)b * NT + t0) * NR + r;
    g_E[a0]            = e0;
    g_E[a0 + NR]       = e1;
    g_E[a0 + 2 * NR]   = e2;
    g_E[a0 + 3 * NR]   = e3;
    g_Dinv[a0]          = __fdividef(1.0f, d0);
    g_Dinv[a0 + NR]     = __fdividef(1.0f, d1);
    g_Dinv[a0 + 2 * NR] = __fdividef(1.0f, d2);
    g_Dinv[a0 + 3 * NR] = __fdividef(1.0f, d3);
}

// ------- K3: M via per-chunk recompute; writes MT[t][i][b] ------------------
__global__ void k_attnM(const float* __restrict__ x) {
    int bc = blockIdx.x;
    int b = bc >> 3, c = bc & 7;
    int i = threadIdx.x;
    float N[NR];
    #pragma unroll
    for (int r = 0; r < NR; r++) N[r] = 0.0f;

    const float* xb = x + ((size_t)b * NT) * NI + i;
    const float* Eb = g_E + ((size_t)b * NT) * NR;
    const float* Db = g_Dinv + ((size_t)b * NT) * NR;

    int tstart = c * 64;
    for (int t = 0; t < tstart; t++) {
        float xv = xb[(size_t)t * NI];
        #pragma unroll
        for (int r = 0; r < NR; r++)
            N[r] = fmaf(Eb[(size_t)t * NR + r], xv, N[r]);
    }
    for (int tl = 0; tl < 64; tl++) {
        int t = tstart + tl;
        float xv = xb[(size_t)t * NI];
        float acc = 0.0f;
        #pragma unroll
        for (int r = 0; r < NR; r++) {
            N[r] = fmaf(Eb[(size_t)t * NR + r], xv, N[r]);
            acc = fmaf(N[r], Db[(size_t)t * NR + r], acc);
        }
        g_MT[((size_t)t * NI + i) * 64 + b] = acc * 0.05f;
    }
}

// ------ K4: clustered LSTM. 16 clusters x 8 CTAs; cluster owns 4 batches ----
// CTA rank j owns hd slice [32j,32j+32) => local cols c: gate g=c>>5, hd=32j+(c&31).
// smem floats: Ws 32768 | Wis 16384 | hsm 2*1024 | Ms 2*512 | gred 2*512 | csm 128 | bsm 128
#define SM_WS   0
#define SM_WIS  (256 * 128)
#define SM_HSM  (SM_WIS + 128 * 128)
#define SM_MS   (SM_HSM + 2 * 1024)
#define SM_GRED (SM_MS + 2 * 512)
#define SM_CSM  (SM_GRED + 2 * 512)
#define SM_BSM  (SM_CSM + 128)
#define LSTM_SMEM ((SM_BSM + 128) * 4)

__global__ void __launch_bounds__(256, 1) __cluster_dims__(CLS, 1, 1)
k_lstm(const float* __restrict__ Whh,
       const float* __restrict__ Wih,
       const float* __restrict__ bias) {
    extern __shared__ float sm[];
    float* Ws   = sm + SM_WS;      // [k=256][c=128]
    float* Wis  = sm + SM_WIS;     // [i=128][c=128]
    float* hsm  = sm + SM_HSM;     // [2][k=256][b=4]
    float* Ms   = sm + SM_MS;      // [2][i=128][b=4]
    float* gred = sm + SM_GRED;    // [u=2][c=128][b=4]
    float* csm  = sm + SM_CSM;     // [128] (hd_local, b)
    float* bsm  = sm + SM_BSM;     // [128]

    int tid = threadIdx.x;
    uint32_t rank;
    asm("mov.u32 %0, %%cluster_ctarank;" : "=r"(rank));
    int j = (int)rank;
    int cl = blockIdx.x >> 3;
    int b0 = cl * 4;

    // load W slices (coalesced over c in 32-wide runs)
    for (int idx = tid; idx < 256 * 128; idx += 256) {
        int k = idx >> 7, c = idx & 127;
        int G = ((c >> 5) << 8) + 32 * j + (c & 31);
        Ws[idx] = Whh[(size_t)k * G4 + G];
    }
    for (int idx = tid; idx < 128 * 128; idx += 256) {
        int k = idx >> 7, c = idx & 127;
        int G = ((c >> 5) << 8) + 32 * j + (c & 31);
        Wis[idx] = Wih[(size_t)k * G4 + G];
    }
    if (tid < 128) {
        int G = ((tid >> 5) << 8) + 32 * j + (tid & 31);
        bsm[tid] = bias[G];
        csm[tid] = 1.0f;
    }
    for (int idx = tid; idx < 1024; idx += 256) hsm[idx] = 1.0f;   // buf 0 = h_0

    // prologue: M_0 -> Ms[0]
    if (tid < 128) {
        float4 m0 = __ldcg((const float4*)(g_MT + (size_t)tid * 64 + b0));
        *(float4*)&Ms[tid * 4] = m0;
    }
    __syncthreads();

    int c = tid & 127, u = tid >> 7;
    int hd_local = (tid < 128) ? (tid >> 2) : 0;
    int bb = tid & 3;
    uint32_t hpush_base = smem_u32(hsm);   // dynamic smem addr, same in all CTAs

    // gx for t=0 (acc init; bias folded into u==0 partial)
    unsigned long long gxa0, gxa1;
    {
        unsigned long long binit = (u == 0) ? dup2(bsm[c]) : 0ull;
        gxa0 = binit; gxa1 = binit;
        const float* mp = Ms + (u * 64) * 4;
        const float* wp = Wis + (u * 64) * 128 + c;
        #pragma unroll 16
        for (int k = 0; k < 64; k++) {
            ulonglong2 mv = *(const ulonglong2*)mp;
            unsigned long long wd = dup2(*wp);
            ffma2(gxa0, mv.x, wd);
            ffma2(gxa1, mv.y, wd);
            mp += 4; wp += 128;
        }
    }

    for (int t = 0; t < NT; t++) {
        int buf = t & 1;

        // prefetch M_{t+1}
        float4 mreg;
        if (tid < 128)
            mreg = __ldcg((const float4*)(g_MT
                    + (size_t)((t + 1) & (NT - 1)) * (NI * 64) + (size_t)tid * 64 + b0));

        // recurrent dot: col c, k in [u*128, u*128+128)
        unsigned long long a0 = gxa0, a1 = gxa1;
        {
            const float* hp = hsm + buf * 1024 + (u * 128) * 4;
            const float* wp = Ws + (u * 128) * 128 + c;
            #pragma unroll 16
            for (int k = 0; k < 128; k++) {
                ulonglong2 hv = *(const ulonglong2*)hp;
                unsigned long long wd = dup2(*wp);
                ffma2(a0, hv.x, wd);
                ffma2(a1, hv.y, wd);
                hp += 4; wp += 128;
            }
        }
        {
            ulonglong2 v; v.x = a0; v.y = a1;
            *(ulonglong2*)&gred[(u * 128 + c) * 4] = v;
        }
        __syncthreads();                               // (1) gred ready

        // gates + DSMEM push of h_{t+1}
        if (tid < 128) {
            float gv[4];
            #pragma unroll
            for (int g = 0; g < 4; g++) {
                int cg = g * 32 + hd_local;
                gv[g] = gred[cg * 4 + bb] + gred[(128 + cg) * 4 + bb];
            }
            float i_t = sigf(gv[0]);
            float f_t = sigf(gv[1]);
            float g_t = tanhfast(gv[2]);
            float o_t = sigf(gv[3]);
            float cc = f_t * csm[tid] + i_t * g_t;
            csm[tid] = cc;
            float hval = o_t * tanhfast(cc);
            uint32_t dst = hpush_base
                         + (uint32_t)(((buf ^ 1) * 1024 + (32 * j + hd_local) * 4 + bb) * 4);
            #pragma unroll
            for (int r = 0; r < CLS; r++) st_cluster_f32(dst, r, hval);
            if (t == NT - 1)
                g_hT[(32 * j + hd_local) * 64 + b0 + bb] = hval;
        }
        // park M_{t+1}
        if (tid < 128)
            *(float4*)&Ms[((t + 1) & 1) * 512 + tid * 4] = mreg;
        __syncthreads();                               // (2) Ms parked, pushes issued

        asm volatile("barrier.cluster.arrive.aligned;" ::: "memory");

        // gx for t+1 (hidden in the cluster-wait window)
        {
            unsigned long long binit = (u == 0) ? dup2(bsm[c]) : 0ull;
            gxa0 = binit; gxa1 = binit;
            const float* mp = Ms + ((t + 1) & 1) * 512 + (u * 64) * 4;
            const float* wp = Wis + (u * 64) * 128 + c;
            #pragma unroll 16
            for (int k = 0; k < 64; k++) {
                ulonglong2 mv = *(const ulonglong2*)mp;
                unsigned long long wd = dup2(*wp);
                ffma2(gxa0, mv.x, wd);
                ffma2(gxa1, mv.y, wd);
                mp += 4; wp += 128;
            }
        }

        asm volatile("barrier.cluster.wait.aligned;" ::: "memory");
    }
}

// ------------------------------ K5: head + softmax --------------------------
__global__ void k_head(const float* __restrict__ Wfc, const float* __restrict__ bfc,
                       float* __restrict__ out) {
    int b = blockIdx.x;
    int lane = threadIdx.x;
    __shared__ float hsm[NH];
    for (int k = lane; k < NH; k += 32) hsm[k] = g_hT[k * 64 + b];
    __syncwarp();
    float l = -1e30f;
    if (lane < NC) {
        float acc = bfc[lane];
        #pragma unroll 8
        for (int k = 0; k < NH; k++) acc = fmaf(hsm[k], Wfc[lane * NH + k], acc);
        l = acc;
    }
    float m = l;
    for (int o = 16; o; o >>= 1) m = fmaxf(m, __shfl_xor_sync(~0u, m, o));
    float e = (lane < NC) ? __expf(l - m) : 0.0f;
    float s = e;
    for (int o = 16; o; o >>= 1) s += __shfl_xor_sync(~0u, s, o);
    if (lane < NC) out[b * NC + lane] = e / s;
}

// ------------------------------ launch --------------------------------------
extern "C" void kernel_launch(void* const* d_in, const int* in_sizes, int n_in,
                              void* d_out, int out_size) {
    const float* x    = (const float*)d_in[0];
    const float* W_ih = (const float*)d_in[1];
    const float* W_hh = (const float*)d_in[2];
    const float* b    = (const float*)d_in[3];
    const float* W1   = (const float*)d_in[4];
    const float* b1   = (const float*)d_in[5];
    const float* W2   = (const float*)d_in[6];
    const float* b2   = (const float*)d_in[7];
    const float* Wfc  = (const float*)d_in[8];
    const float* bfc  = (const float*)d_in[9];
    float* out = (float*)d_out;

    cudaFuncSetAttribute(k_lstm, cudaFuncAttributeMaxDynamicSharedMemorySize, LSTM_SMEM);

    k_scores<<<4096, 256>>>(x, W1, b1, W2, b2);            // idx 0
    k_maxexpdinv<<<NB * NR, 128>>>();                      // idx 1
    k_attnM<<<NB * 8, 128>>>(x);                           // idx 2
    k_lstm<<<128, 256, LSTM_SMEM>>>(W_hh, W_ih, b);        // idx 3 (ncu slot)
    k_head<<<NB, 32>>>(Wfc, bfc, out);                     // idx 4
}

// round 11
// speedup vs baseline: 1.6067x; 1.5750x over previous
#include <cuda_runtime.h>
#include <cuda_bf16.h>
#include <cstdint>

#define NB 64
#define NT 512
#define NI 128
#define NH 256
#define NR 20
#define NDA 50
#define NC 10
#define G4 1024

// ----------------------------- device scratch ------------------------------
__device__ float g_S   [NB * NR * NT];              // [b][r][t]
__device__ float g_E   [NB * NT * NR];              // [b][t][r]
__device__ float g_Dinv[NB * NT * NR];              // [b][t][r]
__device__ float g_MT  [(size_t)NT * NI * NB];      // [t][i][b]
__device__ float g_h   [2][NH * 64];                // [buf][hd*64 + b]
__device__ unsigned g_flags[128];                   // per-block step flags

__device__ __forceinline__ void ffma2(unsigned long long& acc,
                                      unsigned long long a,
                                      unsigned long long b) {
    asm("fma.rn.f32x2 %0, %1, %2, %0;" : "+l"(acc) : "l"(a), "l"(b));
}
__device__ __forceinline__ float sigf(float v) {
    return __fdividef(1.0f, 1.0f + __expf(-v));
}
__device__ __forceinline__ float tanhfast(float v) {
    float ax = fabsf(v);
    float e = __expf(-2.0f * ax);
    float t = __fdividef(1.0f - e, 1.0f + e);
    return copysignf(t, v);
}

// ------------------------------ K1: scores (+init) --------------------------
__global__ void k_scores(const float* __restrict__ x,
                         const float* __restrict__ W1, const float* __restrict__ b1,
                         const float* __restrict__ W2, const float* __restrict__ b2) {
    __shared__ float W1s[NDA][NI + 1];
    __shared__ float W2s[NR][NDA + 1];
    __shared__ float b1s[NDA];
    __shared__ float b2s[NR];
    __shared__ float xr[8][NI];
    __shared__ float ssm[8][NDA + 1];
    int tid = threadIdx.x;

    if (blockIdx.x == 0) {
        for (int j = tid; j < NH * 64; j += 256) g_h[0][j] = 1.0f;
        if (tid < 128) g_flags[tid] = 0u;
    }

    for (int idx = tid; idx < NDA * NI; idx += 256) W1s[idx / NI][idx % NI] = W1[idx];
    for (int idx = tid; idx < NR * NDA; idx += 256) W2s[idx / NDA][idx % NDA] = W2[idx];
    if (tid < NDA) b1s[tid] = b1[tid];
    if (tid < NR)  b2s[tid] = b2[tid];
    __syncthreads();

    int w = tid >> 5, lane = tid & 31;
    int bt = blockIdx.x * 8 + w;
    const float* xp = x + (size_t)bt * NI;
    for (int i = lane; i < NI; i += 32) xr[w][i] = xp[i];
    __syncwarp();
    for (int d = lane; d < NDA; d += 32) {
        float acc = b1s[d];
        #pragma unroll 16
        for (int i = 0; i < NI; i++) acc = fmaf(xr[w][i], W1s[d][i], acc);
        ssm[w][d] = tanhf(acc);
    }
    __syncwarp();
    if (lane < NR) {
        float acc = b2s[lane];
        #pragma unroll
        for (int d = 0; d < NDA; d++) acc = fmaf(ssm[w][d], W2s[lane][d], acc);
        int b = bt >> 9, t = bt & 511;
        g_S[((size_t)b * NR + lane) * NT + t] = acc;
    }
}

// --------------- K2: max over t, exp, prefix-sum denominators ---------------
__global__ void k_maxexpdinv() {
    int br = blockIdx.x;
    int b = br / NR, r = br % NR;
    int tid = threadIdx.x;
    int w = tid >> 5, lane = tid & 31;
    const float* Sp = g_S + (size_t)br * NT;
    float4 v = *(const float4*)(Sp + 4 * tid);

    __shared__ float red[4];
    __shared__ float wsum[4];
    float m = fmaxf(fmaxf(v.x, v.y), fmaxf(v.z, v.w));
    for (int o = 16; o; o >>= 1) m = fmaxf(m, __shfl_xor_sync(~0u, m, o));
    if (lane == 0) red[w] = m;
    __syncthreads();
    m = fmaxf(fmaxf(red[0], red[1]), fmaxf(red[2], red[3]));

    float e0 = __expf(v.x - m), e1 = __expf(v.y - m);
    float e2 = __expf(v.z - m), e3 = __expf(v.w - m);
    float ls = e0 + e1 + e2 + e3;

    float s = ls;
    for (int o = 1; o < 32; o <<= 1) {
        float n = __shfl_up_sync(~0u, s, o);
        if (lane >= o) s += n;
    }
    if (lane == 31) wsum[w] = s;
    __syncthreads();
    float base = 0.0f;
    #pragma unroll
    for (int ww = 0; ww < 4; ww++) if (ww < w) base += wsum[ww];

    float excl = base + s - ls;
    float d0 = excl + e0;
    float d1 = d0 + e1;
    float d2 = d1 + e2;
    float d3 = d2 + e3;

    int t0 = 4 * tid;
    size_t a0 = ((size_t)b * NT + t0) * NR + r;
    g_E[a0]            = e0;
    g_E[a0 + NR]       = e1;
    g_E[a0 + 2 * NR]   = e2;
    g_E[a0 + 3 * NR]   = e3;
    g_Dinv[a0]          = __fdividef(1.0f, d0);
    g_Dinv[a0 + NR]     = __fdividef(1.0f, d1);
    g_Dinv[a0 + 2 * NR] = __fdividef(1.0f, d2);
    g_Dinv[a0 + 3 * NR] = __fdividef(1.0f, d3);
}

// ------- K3: M via per-chunk recompute; writes MT[t][i][b] ------------------
__global__ void k_attnM(const float* __restrict__ x) {
    int bc = blockIdx.x;
    int b = bc >> 3, c = bc & 7;
    int i = threadIdx.x;
    float N[NR];
    #pragma unroll
    for (int r = 0; r < NR; r++) N[r] = 0.0f;

    const float* xb = x + ((size_t)b * NT) * NI + i;
    const float* Eb = g_E + ((size_t)b * NT) * NR;
    const float* Db = g_Dinv + ((size_t)b * NT) * NR;

    int tstart = c * 64;
    for (int t = 0; t < tstart; t++) {
        float xv = xb[(size_t)t * NI];
        #pragma unroll
        for (int r = 0; r < NR; r++)
            N[r] = fmaf(Eb[(size_t)t * NR + r], xv, N[r]);
    }
    for (int tl = 0; tl < 64; tl++) {
        int t = tstart + tl;
        float xv = xb[(size_t)t * NI];
        float acc = 0.0f;
        #pragma unroll
        for (int r = 0; r < NR; r++) {
            N[r] = fmaf(Eb[(size_t)t * NR + r], xv, N[r]);
            acc = fmaf(N[r], Db[(size_t)t * NR + r], acc);
        }
        g_MT[((size_t)t * NI + i) * 64 + b] = acc * 0.05f;
    }
}

// ---------------- K4: fused LSTM, 512 threads (16 warps) --------------------
// 128 persistent blocks. Block bk owns h-dims {2bk,2bk+1} -> 8 gate cols.
// Thread (p=tid&15: 4 batches, qh=(tid>>4)&1: 4 cols, wid=tid>>5: k-16th of 16).
// smem floats: hs 256*68 | Ws2 4096 | Wis2 2048 | Ms 8192 | gred 16*8*64 | csm 128 | bs 8
#define HS_STRIDE 68
#define LSTM_SMEM ((256 * HS_STRIDE + 4096 + 2048 + 8192 + 8192 + 128 + 8) * 4)

__global__ void __launch_bounds__(512, 1) k_lstm(const float* __restrict__ Whh,
                                                 const float* __restrict__ Wih,
                                                 const float* __restrict__ bias) {
    extern __shared__ float sm[];
    float* hs   = sm;                        // [k=256][HS_STRIDE]
    float* Ws2  = hs + 256 * HS_STRIDE;      // Whh slice pair-dup [k=256][16]
    float* Wis2 = Ws2 + 4096;                // Wih slice pair-dup [i=128][16]
    float* Ms   = Wis2 + 2048;               // parked M tile [i=128][b=64]
    float* gred = Ms + 8192;                 // [seg=16][c=8][b=64]
    float* csm  = gred + 8192;               // c state (128)
    float* bs   = csm + 128;                 // bias slice (8)

    int bk = blockIdx.x;
    int tid = threadIdx.x;
    int p = tid & 15, qh = (tid >> 4) & 1, wid = tid >> 5;

    for (int idx = tid; idx < NH * 8; idx += 512) {
        int k = idx >> 3, c = idx & 7;
        float w = Whh[(size_t)k * G4 + (c & 3) * NH + 2 * bk + (c >> 2)];
        Ws2[idx * 2] = w;
        Ws2[idx * 2 + 1] = w;
    }
    for (int idx = tid; idx < NI * 8; idx += 512) {
        int k = idx >> 3, c = idx & 7;
        float w = Wih[(size_t)k * G4 + (c & 3) * NH + 2 * bk + (c >> 2)];
        Wis2[idx * 2] = w;
        Wis2[idx * 2 + 1] = w;
    }
    if (tid < 8) bs[tid] = bias[(tid & 3) * NH + 2 * bk + (tid >> 2)];
    if (tid < 128) csm[tid] = 1.0f;

    // ---- prologue: stage M_0, compute gx partials for t=0 ----
    {
        float4 rm0[4];
        #pragma unroll
        for (int j = 0; j < 4; j++)
            rm0[j] = __ldcg((const float4*)g_MT + tid + j * 512);
        #pragma unroll
        for (int j = 0; j < 4; j++)
            *((float4*)Ms + tid + j * 512) = rm0[j];
    }
    __syncthreads();

    unsigned long long gx[8];
    #pragma unroll
    for (int j = 0; j < 8; j++) gx[j] = 0ull;
    {   // i-segment [wid*8, wid*8+8)
        const float* mp = Ms + (wid * 8) * 64 + 4 * p;
        const float* wp = Wis2 + (wid * 8) * 16 + 8 * qh;
        #pragma unroll
        for (int k = 0; k < 8; k++) {
            ulonglong2 mv = *(const ulonglong2*)mp;
            ulonglong2 w0 = *(const ulonglong2*)wp;
            ulonglong2 w1 = *(const ulonglong2*)(wp + 4);
            ffma2(gx[0], mv.x, w0.x); ffma2(gx[1], mv.y, w0.x);
            ffma2(gx[2], mv.x, w0.y); ffma2(gx[3], mv.y, w0.y);
            ffma2(gx[4], mv.x, w1.x); ffma2(gx[5], mv.y, w1.x);
            ffma2(gx[6], mv.x, w1.y); ffma2(gx[7], mv.y, w1.y);
            mp += 64; wp += 16;
        }
    }

    int bbg = tid & 63, hig = (tid >> 6) & 1;   // gate mapping (tid<128)

    for (int t = 0; t < NT; t++) {
        const float* hin = g_h[t & 1];
        float* hout = g_h[(t + 1) & 1];
        const float* mnext = g_MT + (size_t)((t + 1) & (NT - 1)) * (NI * 64);

        // issue h loads (critical path) then M_{t+1}
        float4 rh[8], rm[4];
        #pragma unroll
        for (int j = 0; j < 8; j++)
            rh[j] = __ldcg((const float4*)hin + tid + j * 512);
        #pragma unroll
        for (int j = 0; j < 4; j++)
            rm[j] = __ldcg((const float4*)mnext + tid + j * 512);

        // stage h into hs (stride HS_STRIDE)
        #pragma unroll
        for (int j = 0; j < 8; j++) {
            int idx = tid + j * 512;                // float4 index
            int row = idx >> 4, c4 = (idx & 15) * 4;
            *(float4*)(hs + row * HS_STRIDE + c4) = rh[j];
        }
        __syncthreads();                            // (1) hs ready

        unsigned long long a[8];
        #pragma unroll
        for (int j = 0; j < 8; j++) a[j] = gx[j];
        {   // recurrent dot: warp's k-16th [wid*16, wid*16+16)
            const float* hp = hs + (wid * 16) * HS_STRIDE + 4 * p;
            const float* wp = Ws2 + (wid * 16) * 16 + 8 * qh;
            #pragma unroll 8
            for (int k = 0; k < 16; k++) {
                ulonglong2 hv = *(const ulonglong2*)hp;
                ulonglong2 w0 = *(const ulonglong2*)wp;
                ulonglong2 w1 = *(const ulonglong2*)(wp + 4);
                ffma2(a[0], hv.x, w0.x); ffma2(a[1], hv.y, w0.x);
                ffma2(a[2], hv.x, w0.y); ffma2(a[3], hv.y, w0.y);
                ffma2(a[4], hv.x, w1.x); ffma2(a[5], hv.y, w1.x);
                ffma2(a[6], hv.x, w1.y); ffma2(a[7], hv.y, w1.y);
                hp += HS_STRIDE; wp += 16;
            }
        }
        {
            float* gr = gred + (wid * 8 + 4 * qh) * 64 + 4 * p;
            ulonglong2 v;
            v.x = a[0]; v.y = a[1]; *(ulonglong2*)gr         = v;
            v.x = a[2]; v.y = a[3]; *(ulonglong2*)(gr + 64)  = v;
            v.x = a[4]; v.y = a[5]; *(ulonglong2*)(gr + 128) = v;
            v.x = a[6]; v.y = a[7]; *(ulonglong2*)(gr + 192) = v;
        }
        // park M_{t+1}
        #pragma unroll
        for (int j = 0; j < 4; j++)
            *((float4*)Ms + tid + j * 512) = rm[j];
        __syncthreads();                            // (2) gred + Ms ready

        if (tid < 128) {
            float gv[4];
            #pragma unroll
            for (int g = 0; g < 4; g++) {
                int c = hig * 4 + g;
                float s = 0.0f;
                #pragma unroll
                for (int o = 0; o < 16; o++) s += gred[(o * 8 + c) * 64 + bbg];
                gv[g] = s + bs[c];
            }
            float i_t = sigf(gv[0]);
            float f_t = sigf(gv[1]);
            float g_t = tanhfast(gv[2]);
            float o_t = sigf(gv[3]);
            float cc = f_t * csm[tid] + i_t * g_t;
            csm[tid] = cc;
            __stcg(&hout[(2 * bk + hig) * 64 + bbg], o_t * tanhfast(cc));
        }
        __syncthreads();                            // (3) all h stores issued

        if (tid == 0)
            asm volatile("st.release.gpu.global.u32 [%0], %1;"
                         :: "l"(&g_flags[bk]), "r"((unsigned)(t + 1)) : "memory");

        // gx for t+1 in the straggle window
        #pragma unroll
        for (int j = 0; j < 8; j++) gx[j] = 0ull;
        {
            const float* mp = Ms + (wid * 8) * 64 + 4 * p;
            const float* wp = Wis2 + (wid * 8) * 16 + 8 * qh;
            #pragma unroll
            for (int k = 0; k < 8; k++) {
                ulonglong2 mv = *(const ulonglong2*)mp;
                ulonglong2 w0 = *(const ulonglong2*)wp;
                ulonglong2 w1 = *(const ulonglong2*)(wp + 4);
                ffma2(gx[0], mv.x, w0.x); ffma2(gx[1], mv.y, w0.x);
                ffma2(gx[2], mv.x, w0.y); ffma2(gx[3], mv.y, w0.y);
                ffma2(gx[4], mv.x, w1.x); ffma2(gx[5], mv.y, w1.x);
                ffma2(gx[6], mv.x, w1.y); ffma2(gx[7], mv.y, w1.y);
                mp += 64; wp += 16;
            }
        }

        // wait: 128 parallel pollers, one flag each
        if (tid < 128) {
            unsigned v;
            do {
                asm volatile("ld.acquire.gpu.global.u32 %0, [%1];"
                             : "=r"(v) : "l"(&g_flags[tid]));
            } while (v < (unsigned)(t + 1));
        }
        __syncthreads();                            // (4) barrier release
    }
}

// ------------------------------ K5: head + softmax --------------------------
__global__ void k_head(const float* __restrict__ Wfc, const float* __restrict__ bfc,
                       float* __restrict__ out) {
    int b = blockIdx.x;
    int lane = threadIdx.x;
    __shared__ float hsm[NH];
    for (int k = lane; k < NH; k += 32) hsm[k] = g_h[0][k * 64 + b];
    __syncwarp();
    float l = -1e30f;
    if (lane < NC) {
        float acc = bfc[lane];
        #pragma unroll 8
        for (int k = 0; k < NH; k++) acc = fmaf(hsm[k], Wfc[lane * NH + k], acc);
        l = acc;
    }
    float m = l;
    for (int o = 16; o; o >>= 1) m = fmaxf(m, __shfl_xor_sync(~0u, m, o));
    float e = (lane < NC) ? __expf(l - m) : 0.0f;
    float s = e;
    for (int o = 16; o; o >>= 1) s += __shfl_xor_sync(~0u, s, o);
    if (lane < NC) out[b * NC + lane] = e / s;
}

// ------------------------------ launch --------------------------------------
extern "C" void kernel_launch(void* const* d_in, const int* in_sizes, int n_in,
                              void* d_out, int out_size) {
    const float* x    = (const float*)d_in[0];
    const float* W_ih = (const float*)d_in[1];
    const float* W_hh = (const float*)d_in[2];
    const float* b    = (const float*)d_in[3];
    const float* W1   = (const float*)d_in[4];
    const float* b1   = (const float*)d_in[5];
    const float* W2   = (const float*)d_in[6];
    const float* b2   = (const float*)d_in[7];
    const float* Wfc  = (const float*)d_in[8];
    const float* bfc  = (const float*)d_in[9];
    float* out = (float*)d_out;

    cudaFuncSetAttribute(k_lstm, cudaFuncAttributeMaxDynamicSharedMemorySize, LSTM_SMEM);

    k_scores<<<4096, 256>>>(x, W1, b1, W2, b2);            // idx 0
    k_maxexpdinv<<<NB * NR, 128>>>();                      // idx 1
    k_attnM<<<NB * 8, 128>>>(x);                           // idx 2
    k_lstm<<<128, 512, LSTM_SMEM>>>(W_hh, W_ih, b);        // idx 3 (ncu slot)
    k_head<<<NB, 32>>>(Wfc, bfc, out);                     // idx 4
}